// round 14
// baseline (speedup 1.0000x reference)
#include <cuda_runtime.h>
#include <cuda_bf16.h>

// DurationCalculator:
//   weights_argmax[b,y] = duration[b,y] + (y < output_length[b] ? 0 : -10000)
//   durations[b,x]      = count over y of (weights_argmax[b,y] == x), 0 <= x < X
// Output (float32): [ weights_argmax (B*Y) | durations (B*X) ]
//
// ATOMS-free histogram. Model: all prior ~6us variants were bound by the smem
// atomic unit (~2 cyc/lane * ~524K valid increments). This kernel replaces
// atomics with crossbar traffic:
//   Phase A: 16 warps stream, write w_out, and ballot-compact valid values
//            into per-warp u16 queues (warp-uniform register tail; NO atomics)
//   Phase B: warp 0 drains queues into hist8[bin][lane] byte columns --
//            lane-exclusive column => race-free plain LDS.U8/STS.U8.
//            (per-(bin,lane) count <= ceil(Y/32)=128 < 255: no u8 overflow)
//   Merge:   per bin, sum 32 bytes via 2x LDS.128 + 8x dp4a -> float4 store.
// Host falls back to a simple smem-atomic kernel if shapes exceed buffers.

#ifndef MASK_PENALTY
#define MASK_PENALTY (-10000)
#endif

#define NT 512
#define NW (NT / 32)
#define MAXX 1024
#define QTOT 4608

__global__ void __launch_bounds__(NT)
duration_calc_kernel(const int* __restrict__ duration,
                     const int* __restrict__ output_length,
                     float* __restrict__ w_out,
                     float* __restrict__ h_out,
                     int Y, int X, int qcap)
{
    __shared__ unsigned char  hist8[MAXX * 32];   // [bin][lane] byte counters, 32 KB
    __shared__ unsigned short q[QTOT];            // per-warp queue segments
    __shared__ int qlen[NW];

    const int b    = blockIdx.x;
    const int tid  = threadIdx.x;
    const int wid  = tid >> 5;
    const int lane = tid & 31;

    // Zero the used hist8 region (X*32 bytes, 16B-vectorized)
    {
        int4* hz = reinterpret_cast<int4*>(hist8);
        const int nz = (X * 32) >> 4;
        const int4 z = make_int4(0, 0, 0, 0);
        for (int i = tid; i < nz; i += NT) hz[i] = z;
    }
    __syncthreads();

    const int L = output_length[b];

    const int4* __restrict__ dur4 = reinterpret_cast<const int4*>(duration + (size_t)b * Y);
    float4* __restrict__ w4       = reinterpret_cast<float4*>(w_out + (size_t)b * Y);
    const int n4     = Y >> 2;
    const int kiters = (n4 + NT - 1) / NT;
    const int ytail0 = n4 << 2;
    const int titers = (Y - ytail0 + NT - 1) / NT;   // 0 for Y%4==0

    unsigned short* __restrict__ myq = q + wid * qcap;
    int tail = 0;   // warp-uniform (ballot popc accumulation)

    // ---- Phase A: stream + write w_out + compact valid values ----
    for (int k = 0; k < kiters; k++) {
        const int i  = k * NT + tid;
        const bool ip = i < n4;
        const int y  = i << 2;
        int4 d = ip ? dur4[i] : make_int4(-1, -1, -1, -1);
        if (ip) {
            float4 w;
            w.x = (float)(d.x + ((y + 0) < L ? 0 : MASK_PENALTY));
            w.y = (float)(d.y + ((y + 1) < L ? 0 : MASK_PENALTY));
            w.z = (float)(d.z + ((y + 2) < L ? 0 : MASK_PENALTY));
            w.w = (float)(d.w + ((y + 3) < L ? 0 : MASK_PENALTY));
            w4[i] = w;
        }
        #pragma unroll
        for (int s = 0; s < 4; s++) {
            const int v = (s == 0) ? d.x : (s == 1) ? d.y : (s == 2) ? d.z : d.w;
            const bool valid = ip && ((y + s) < L) && ((unsigned)v < (unsigned)X);
            const unsigned m = __ballot_sync(0xFFFFFFFFu, valid);
            if (valid)
                myq[tail + __popc(m & ((1u << lane) - 1))] = (unsigned short)v;
            tail += __popc(m);
        }
    }
    // Scalar tail (Y % 4 != 0); warp-uniform trip count keeps ballot collective.
    for (int k = 0; k < titers; k++) {
        const int y  = ytail0 + k * NT + tid;
        const bool ip = y < Y;
        int v = -1;
        if (ip) {
            v = duration[(size_t)b * Y + y];
            w_out[(size_t)b * Y + y] = (float)(v + (y < L ? 0 : MASK_PENALTY));
        }
        const bool valid = ip && (y < L) && ((unsigned)v < (unsigned)X);
        const unsigned m = __ballot_sync(0xFFFFFFFFu, valid);
        if (valid)
            myq[tail + __popc(m & ((1u << lane) - 1))] = (unsigned short)v;
        tail += __popc(m);
    }
    if (lane == 0) qlen[wid] = tail;
    __syncthreads();

    // ---- Phase B: warp 0 drains queues into lane-private byte columns ----
    if (wid == 0) {
        for (int s = 0; s < NW; s++) {
            const unsigned short* __restrict__ sq = q + s * qcap;
            const int n = qlen[s];
            #pragma unroll 4
            for (int i = lane; i < n; i += 32) {
                const int v = sq[i];
                hist8[v * 32 + lane]++;    // lane-exclusive column: race-free
            }
        }
    }
    __syncthreads();

    // ---- Merge: sum 32 bytes per bin (dp4a), write float ----
    float* __restrict__ hrow = h_out + (size_t)b * X;
    const unsigned ones = 0x01010101u;
    for (int bin4 = tid; bin4 < (X >> 2); bin4 += NT) {
        float o[4];
        #pragma unroll
        for (int j = 0; j < 4; j++) {
            const int bin = (bin4 << 2) + j;
            const uint4* p = reinterpret_cast<const uint4*>(hist8 + bin * 32);
            uint4 a = p[0], c = p[1];
            unsigned acc = 0;
            acc = __dp4a(a.x, ones, acc);
            acc = __dp4a(a.y, ones, acc);
            acc = __dp4a(a.z, ones, acc);
            acc = __dp4a(a.w, ones, acc);
            acc = __dp4a(c.x, ones, acc);
            acc = __dp4a(c.y, ones, acc);
            acc = __dp4a(c.z, ones, acc);
            acc = __dp4a(c.w, ones, acc);
            o[j] = (float)acc;
        }
        reinterpret_cast<float4*>(hrow)[bin4] = make_float4(o[0], o[1], o[2], o[3]);
    }
    for (int bin = (X & ~3) + tid; bin < X; bin += NT) {   // X%4 tail bins
        const uint4* p = reinterpret_cast<const uint4*>(hist8 + bin * 32);
        uint4 a = p[0], c = p[1];
        unsigned acc = 0;
        acc = __dp4a(a.x, ones, acc); acc = __dp4a(a.y, ones, acc);
        acc = __dp4a(a.z, ones, acc); acc = __dp4a(a.w, ones, acc);
        acc = __dp4a(c.x, ones, acc); acc = __dp4a(c.y, ones, acc);
        acc = __dp4a(c.z, ones, acc); acc = __dp4a(c.w, ones, acc);
        hrow[bin] = (float)acc;
    }
}

// Fallback: proven smem-atomic version (R3 shape) for out-of-range shapes.
__global__ void __launch_bounds__(512)
duration_calc_fallback(const int* __restrict__ duration,
                       const int* __restrict__ output_length,
                       float* __restrict__ w_out,
                       float* __restrict__ h_out,
                       int Y, int X)
{
    extern __shared__ int hist[];
    const int b = blockIdx.x, tid = threadIdx.x, nt = blockDim.x;
    for (int i = tid; i < X; i += nt) hist[i] = 0;
    __syncthreads();
    const int L = output_length[b];
    for (int y = tid; y < Y; y += nt) {
        int w = duration[(size_t)b * Y + y] + (y < L ? 0 : MASK_PENALTY);
        w_out[(size_t)b * Y + y] = (float)w;
        if ((unsigned)w < (unsigned)X) atomicAdd(&hist[w], 1);
    }
    __syncthreads();
    float* hrow = h_out + (size_t)b * X;
    for (int i = tid; i < X; i += nt) hrow[i] = (float)hist[i];
}

extern "C" void kernel_launch(void* const* d_in, const int* in_sizes, int n_in,
                              void* d_out, int out_size)
{
    const int* duration      = (const int*)d_in[0];
    const int* output_length = (const int*)d_in[1];

    const int B = in_sizes[1];          // 256
    const int Y = in_sizes[0] / B;      // 4096
    const int X = out_size / B - Y;     // 1024

    float* w_out = (float*)d_out;                   // weights_argmax: B*Y
    float* h_out = (float*)d_out + (size_t)B * Y;   // durations:      B*X

    const int n4     = Y >> 2;
    const int kiters = (n4 + NT - 1) / NT;
    const int ytail0 = n4 << 2;
    const int titers = (Y - ytail0 + NT - 1) / NT;
    const int qcap   = 128 * kiters + 32 * titers;  // max values per warp

    if (X <= MAXX && NW * qcap <= QTOT) {
        duration_calc_kernel<<<B, NT>>>(duration, output_length,
                                        w_out, h_out, Y, X, qcap);
    } else {
        duration_calc_fallback<<<B, 512, (size_t)X * sizeof(int)>>>(
            duration, output_length, w_out, h_out, Y, X);
    }
}

// round 16
// speedup vs baseline: 2.8792x; 2.8792x over previous
#include <cuda_runtime.h>
#include <cuda_bf16.h>

// DurationCalculator:
//   weights_argmax[b,y] = duration[b,y] + (y < output_length[b] ? 0 : -10000)
//   durations[b,x]      = count over y of (weights_argmax[b,y] == x), 0 <= x < X
// Output (float32): [ weights_argmax (B*Y) | durations (B*X) ]
//
// One CTA per row, 256 threads, smem-atomic histogram. NO I2F anywhere:
// int->float via exponent-bias trick. For v in [0, 2^22):
//   float(v - 16384) = as_float(0x4B400000 + v) - 12599296.0f
// Mask folds into one selected constant:
//   valid : t = d + 0x4B404000  (= bias + 16384)        -> f = d
//   masked: t = d + 0x4B4018F0  (= bias + 16384 - 10000) -> f = d - 10000
// One IADD3 + one full-rate FADD per element replaces the I2F chain.

#ifndef MASK_PENALTY
#define MASK_PENALTY (-10000)
#endif

#define FBIAS       12599296.0f      // 2^23 + 2^22 (=12582912) + 16384
#define C_VALID     0x4B404000u      // 0x4B400000 + 16384
#define C_MASKED    0x4B4018F0u      // 0x4B400000 + 16384 - 10000

__global__ void __launch_bounds__(256)
duration_calc_kernel(const int* __restrict__ duration,
                     const int* __restrict__ output_length,
                     float* __restrict__ w_out,
                     float* __restrict__ h_out,
                     int Y, int X)
{
    extern __shared__ int hist[];   // X bins
    const int b   = blockIdx.x;
    const int tid = threadIdx.x;
    const int nt  = blockDim.x;     // 256

    for (int i = tid; i < X; i += nt) hist[i] = 0;
    __syncthreads();

    const int L = output_length[b];

    const int4* __restrict__ dur4 = reinterpret_cast<const int4*>(duration + (size_t)b * Y);
    float4* __restrict__ w4       = reinterpret_cast<float4*>(w_out + (size_t)b * Y);
    const int n4 = Y >> 2;          // 1024 for Y=4096

    // 8 elems/thread: 2 front-batched int4 loads per iteration (MLP=2).
    for (int base = tid; base < n4; base += nt * 2) {
        const int i0 = base;
        const int i1 = base + nt;
        const bool p1 = i1 < n4;

        int4 d0 = dur4[i0];
        int4 d1 = p1 ? dur4[i1] : make_int4(0, 0, 0, 0);

        #define PROC(dd, ii, pp)                                               \
        do {                                                                   \
            if (pp) {                                                          \
                const int y = (ii) << 2;                                       \
                const bool v0 = (y + 0) < L;                                   \
                const bool v1 = (y + 1) < L;                                   \
                const bool v2 = (y + 2) < L;                                   \
                const bool v3 = (y + 3) < L;                                   \
                float4 w;                                                      \
                w.x = __uint_as_float((unsigned)dd.x + (v0 ? C_VALID : C_MASKED)) - FBIAS; \
                w.y = __uint_as_float((unsigned)dd.y + (v1 ? C_VALID : C_MASKED)) - FBIAS; \
                w.z = __uint_as_float((unsigned)dd.z + (v2 ? C_VALID : C_MASKED)) - FBIAS; \
                w.w = __uint_as_float((unsigned)dd.w + (v3 ? C_VALID : C_MASKED)) - FBIAS; \
                w4[ii] = w;                                                    \
                if (v0 && (unsigned)dd.x < (unsigned)X) atomicAdd(&hist[dd.x], 1); \
                if (v1 && (unsigned)dd.y < (unsigned)X) atomicAdd(&hist[dd.y], 1); \
                if (v2 && (unsigned)dd.z < (unsigned)X) atomicAdd(&hist[dd.z], 1); \
                if (v3 && (unsigned)dd.w < (unsigned)X) atomicAdd(&hist[dd.w], 1); \
            }                                                                  \
        } while (0)

        PROC(d0, i0, true);
        PROC(d1, i1, p1);
        #undef PROC
    }

    // Scalar tail for Y not a multiple of 4 (no-op for Y=4096)
    for (int y = (n4 << 2) + tid; y < Y; y += nt) {
        const int d = duration[(size_t)b * Y + y];
        const bool v = y < L;
        w_out[(size_t)b * Y + y] =
            __uint_as_float((unsigned)d + (v ? C_VALID : C_MASKED)) - FBIAS;
        if (v && (unsigned)d < (unsigned)X) atomicAdd(&hist[d], 1);
    }

    __syncthreads();

    // Histogram -> float output; counts < 2^22 so the same trick applies:
    // float(c) = as_float(0x4B400000 + c) - 12582912.0f
    float* __restrict__ hrow = h_out + (size_t)b * X;
    if ((X & 3) == 0) {
        float4* __restrict__ hrow4 = reinterpret_cast<float4*>(hrow);
        for (int i = tid; i < (X >> 2); i += nt) {
            float4 v;
            v.x = __uint_as_float(0x4B400000u + (unsigned)hist[(i << 2) + 0]) - 12582912.0f;
            v.y = __uint_as_float(0x4B400000u + (unsigned)hist[(i << 2) + 1]) - 12582912.0f;
            v.z = __uint_as_float(0x4B400000u + (unsigned)hist[(i << 2) + 2]) - 12582912.0f;
            v.w = __uint_as_float(0x4B400000u + (unsigned)hist[(i << 2) + 3]) - 12582912.0f;
            hrow4[i] = v;
        }
    } else {
        for (int i = tid; i < X; i += nt)
            hrow[i] = __uint_as_float(0x4B400000u + (unsigned)hist[i]) - 12582912.0f;
    }
}

extern "C" void kernel_launch(void* const* d_in, const int* in_sizes, int n_in,
                              void* d_out, int out_size)
{
    const int* duration      = (const int*)d_in[0];
    const int* output_length = (const int*)d_in[1];

    const int B = in_sizes[1];          // 256
    const int Y = in_sizes[0] / B;      // 4096
    const int X = out_size / B - Y;     // 1024

    float* w_out = (float*)d_out;                   // weights_argmax: B*Y
    float* h_out = (float*)d_out + (size_t)B * Y;   // durations:      B*X

    const int threads = 256;
    const size_t smem = (size_t)X * sizeof(int);
    duration_calc_kernel<<<B, threads, smem>>>(duration, output_length,
                                               w_out, h_out, Y, X);
}